// round 2
// baseline (speedup 1.0000x reference)
#include <cuda_runtime.h>
#include <math.h>

#define B_    2
#define NQ    1024
#define NK    2048
#define DIM_  512
#define HID_  512
#define H_    8
#define HD_   64
#define RBH   64
#define LUT_T 2048

// Static device scratch (no runtime allocation allowed)
__device__ float g_Q[(size_t)B_ * NQ * HID_];          //  4 MB
__device__ float g_K[(size_t)B_ * NK * HID_];          //  8 MB
__device__ float g_V[(size_t)B_ * NK * HID_];          //  8 MB
__device__ float g_attn[(size_t)B_ * NQ * HID_];       //  4 MB
__device__ float g_lut[H_ * LUT_T];                    // 64 KB  per-head bias LUT
__device__ unsigned int g_maxbits[2];                  // max |qc|, max |kc| (float bits)
__device__ float g_inv_step;                           // LUT index scale

// ---------------------------------------------------------------------------
// LUT pipeline: init -> max coord norms -> build per-head bias(d) tables
// ---------------------------------------------------------------------------
__global__ void init_kernel() {
    if (threadIdx.x < 2) g_maxbits[threadIdx.x] = 0u;
}

__global__ __launch_bounds__(256) void norm_kernel(
    const float* __restrict__ qc, const float* __restrict__ kc)
{
    const int NQT = B_ * NQ;
    const int NKT = B_ * NK;
    int i = blockIdx.x * 256 + threadIdx.x;
    float n = 0.f;
    int which = 0;
    if (i < NQT) {
        float x = qc[i*3], y = qc[i*3+1], z = qc[i*3+2];
        n = sqrtf(fmaf(x,x,fmaf(y,y,z*z)));
    } else if (i < NQT + NKT) {
        int j = i - NQT;
        float x = kc[j*3], y = kc[j*3+1], z = kc[j*3+2];
        n = sqrtf(fmaf(x,x,fmaf(y,y,z*z)));
        which = 1;
    }
    // warp reduce max within each 'which' group (groups are contiguous; the
    // one straddling warp handles both via two atomics — cheap anyway)
    unsigned int bits = __float_as_uint(n);
    atomicMax(&g_maxbits[which], bits);
}

__global__ __launch_bounds__(256) void lut_kernel(
    const float* __restrict__ W1, const float* __restrict__ b1,
    const float* __restrict__ W2, const float* __restrict__ b2)
{
    __shared__ float sW1[RBH], sb1[RBH], sW2[RBH * H_];
    int t = threadIdx.x;
    if (t < RBH) { sW1[t] = W1[t]; sb1[t] = b1[t]; }
    for (int i = t; i < RBH * H_; i += 256) sW2[i] = W2[i];
    __syncthreads();

    float dmax = __uint_as_float(g_maxbits[0]) + __uint_as_float(g_maxbits[1]) + 1e-3f;
    float step = dmax / (float)(LUT_T - 1);
    if (blockIdx.x == 0 && t == 0) g_inv_step = 1.0f / step;

    int i = blockIdx.x * 256 + t;
    if (i >= LUT_T) return;
    float d = step * (float)i;

    float o[H_];
    #pragma unroll
    for (int hh = 0; hh < H_; hh++) o[hh] = b2[hh];
    #pragma unroll 8
    for (int j = 0; j < RBH; j++) {
        float x = fmaf(d, sW1[j], sb1[j]);
        float s = __fdividef(x, 1.0f + __expf(-x));
        #pragma unroll
        for (int hh = 0; hh < H_; hh++)
            o[hh] = fmaf(s, sW2[j * H_ + hh], o[hh]);
    }
    #pragma unroll
    for (int hh = 0; hh < H_; hh++) g_lut[hh * LUT_T + i] = o[hh];
}

// ---------------------------------------------------------------------------
// fp32 GEMM: C[M,N] = A[M,K] @ B[K,N]. 128x64 tile, BK=16, 256 threads,
// 8x4 micro-tile, ping-pong double-buffered SMEM (1 sync / k-tile).
// ---------------------------------------------------------------------------
#define GBM 128
#define GBN 64
#define GBK 16

__global__ __launch_bounds__(256) void gemm_kernel(
    const float* __restrict__ A, const float* __restrict__ Bm,
    float* __restrict__ C, int M, int N, int K)
{
    __shared__ float As[2][GBK][GBM + 4];
    __shared__ float Bs[2][GBK][GBN + 4];

    const int tid = threadIdx.x;
    const int tx  = tid & 15;       // 0..15 -> 4-wide col
    const int ty  = tid >> 4;       // 0..15 -> 8-wide row
    const int row0 = blockIdx.y * GBM;
    const int col0 = blockIdx.x * GBN;

    // load indices
    const int am = tid >> 1;          // 0..127
    const int av = (tid & 1) * 8;     // 0 or 8
    const int bk = tid >> 4;          // 0..15
    const int bn = (tid & 15) * 4;    // 0..60

    float acc[8][4] = {};

    // preload tile 0
    float4 a0 = *reinterpret_cast<const float4*>(&A[(size_t)(row0 + am) * K + av]);
    float4 a1 = *reinterpret_cast<const float4*>(&A[(size_t)(row0 + am) * K + av + 4]);
    float4 b0 = *reinterpret_cast<const float4*>(&Bm[(size_t)bk * N + col0 + bn]);
    {
        As[0][av+0][am]=a0.x; As[0][av+1][am]=a0.y; As[0][av+2][am]=a0.z; As[0][av+3][am]=a0.w;
        As[0][av+4][am]=a1.x; As[0][av+5][am]=a1.y; As[0][av+6][am]=a1.z; As[0][av+7][am]=a1.w;
        *reinterpret_cast<float4*>(&Bs[0][bk][bn]) = b0;
    }
    __syncthreads();

    int buf = 0;
    for (int k0 = 0; k0 < K; k0 += GBK) {
        const int nk = k0 + GBK;
        float4 na0, na1, nb0;
        if (nk < K) {
            na0 = *reinterpret_cast<const float4*>(&A[(size_t)(row0 + am) * K + nk + av]);
            na1 = *reinterpret_cast<const float4*>(&A[(size_t)(row0 + am) * K + nk + av + 4]);
            nb0 = *reinterpret_cast<const float4*>(&Bm[(size_t)(nk + bk) * N + col0 + bn]);
        }

        #pragma unroll
        for (int kk = 0; kk < GBK; kk++) {
            float4 A0 = *reinterpret_cast<const float4*>(&As[buf][kk][ty * 8]);
            float4 A1 = *reinterpret_cast<const float4*>(&As[buf][kk][ty * 8 + 4]);
            float4 B0 = *reinterpret_cast<const float4*>(&Bs[buf][kk][tx * 4]);
            float av8[8] = {A0.x,A0.y,A0.z,A0.w,A1.x,A1.y,A1.z,A1.w};
            float bv[4]  = {B0.x,B0.y,B0.z,B0.w};
            #pragma unroll
            for (int i = 0; i < 8; i++)
                #pragma unroll
                for (int j = 0; j < 4; j++)
                    acc[i][j] = fmaf(av8[i], bv[j], acc[i][j]);
        }

        if (nk < K) {
            int nb = buf ^ 1;
            As[nb][av+0][am]=na0.x; As[nb][av+1][am]=na0.y; As[nb][av+2][am]=na0.z; As[nb][av+3][am]=na0.w;
            As[nb][av+4][am]=na1.x; As[nb][av+5][am]=na1.y; As[nb][av+6][am]=na1.z; As[nb][av+7][am]=na1.w;
            *reinterpret_cast<float4*>(&Bs[nb][bk][bn]) = nb0;
            __syncthreads();
            buf = nb;
        }
    }

    #pragma unroll
    for (int i = 0; i < 8; i++) {
        float4 o = make_float4(acc[i][0], acc[i][1], acc[i][2], acc[i][3]);
        *reinterpret_cast<float4*>(
            &C[(size_t)(row0 + ty * 8 + i) * N + col0 + tx * 4]) = o;
    }
}

// ---------------------------------------------------------------------------
// Flash attention with on-the-fly distance + LUT bias.
// grid: (NQ/QT, H, B), block QT threads (1 q row / thread).
// ---------------------------------------------------------------------------
#define QT 64
#define KT 32

__global__ __launch_bounds__(QT) void attn_kernel(const float* __restrict__ qc,
                                                  const float* __restrict__ kc)
{
    __shared__ float Ks[KT][HD_];
    __shared__ float Vs[KT][HD_];
    __shared__ float skc[KT * 3];
    __shared__ float slut[LUT_T];

    const int b = blockIdx.z;
    const int h = blockIdx.y;
    const int q = blockIdx.x * QT + threadIdx.x;
    const float scale = 0.125f;  // HD^-0.5

    // stage this head's LUT
    for (int i = threadIdx.x; i < LUT_T; i += QT) slut[i] = g_lut[h * LUT_T + i];
    const float inv_step = g_inv_step;

    // per-thread q coordinate
    const float qcx = qc[((size_t)b * NQ + q) * 3 + 0];
    const float qcy = qc[((size_t)b * NQ + q) * 3 + 1];
    const float qcz = qc[((size_t)b * NQ + q) * 3 + 2];

    const float* qrow = g_Q + ((size_t)(b * NQ + q)) * HID_ + h * HD_;
    float qr[HD_];
    #pragma unroll
    for (int d4 = 0; d4 < HD_; d4 += 4) {
        float4 v = *reinterpret_cast<const float4*>(&qrow[d4]);
        qr[d4] = v.x * scale; qr[d4+1] = v.y * scale;
        qr[d4+2] = v.z * scale; qr[d4+3] = v.w * scale;
    }

    float acc[HD_];
    #pragma unroll
    for (int d = 0; d < HD_; d++) acc[d] = 0.f;
    float mrun = -INFINITY, lrun = 0.f;

    const float* Kp = g_K + ((size_t)b * NK) * HID_ + h * HD_;
    const float* Vp = g_V + ((size_t)b * NK) * HID_ + h * HD_;
    const float* kcb = kc + (size_t)b * NK * 3;

    for (int k0 = 0; k0 < NK; k0 += KT) {
        __syncthreads();
        for (int i = threadIdx.x; i < KT * HD_ / 4; i += QT) {
            const int kk = i >> 4;
            const int d4 = (i & 15) * 4;
            *reinterpret_cast<float4*>(&Ks[kk][d4]) =
                *reinterpret_cast<const float4*>(&Kp[(size_t)(k0 + kk) * HID_ + d4]);
            *reinterpret_cast<float4*>(&Vs[kk][d4]) =
                *reinterpret_cast<const float4*>(&Vp[(size_t)(k0 + kk) * HID_ + d4]);
        }
        for (int i = threadIdx.x; i < KT * 3; i += QT)
            skc[i] = kcb[(size_t)k0 * 3 + i];
        __syncthreads();

        #pragma unroll 2
        for (int kk = 0; kk < KT; kk++) {
            // distance + LUT bias
            float dx = qcx - skc[kk*3+0];
            float dy = qcy - skc[kk*3+1];
            float dz = qcz - skc[kk*3+2];
            float dd = sqrtf(fmaf(dx,dx,fmaf(dy,dy,dz*dz)));
            float t  = dd * inv_step;
            int   ii = (int)t;
            ii = (ii > LUT_T - 2) ? (LUT_T - 2) : ii;
            float frac = t - (float)ii;
            float lo = slut[ii], hi = slut[ii + 1];
            float bias = fmaf(frac, hi - lo, lo);

            // QK dot, 4 independent chains
            float s0 = bias, s1 = 0.f, s2 = 0.f, s3 = 0.f;
            #pragma unroll
            for (int d4 = 0; d4 < HD_; d4 += 16) {
                float4 k0v = *reinterpret_cast<const float4*>(&Ks[kk][d4]);
                float4 k1v = *reinterpret_cast<const float4*>(&Ks[kk][d4+4]);
                float4 k2v = *reinterpret_cast<const float4*>(&Ks[kk][d4+8]);
                float4 k3v = *reinterpret_cast<const float4*>(&Ks[kk][d4+12]);
                s0 = fmaf(qr[d4],    k0v.x, s0); s0 = fmaf(qr[d4+1],  k0v.y, s0);
                s0 = fmaf(qr[d4+2],  k0v.z, s0); s0 = fmaf(qr[d4+3],  k0v.w, s0);
                s1 = fmaf(qr[d4+4],  k1v.x, s1); s1 = fmaf(qr[d4+5],  k1v.y, s1);
                s1 = fmaf(qr[d4+6],  k1v.z, s1); s1 = fmaf(qr[d4+7],  k1v.w, s1);
                s2 = fmaf(qr[d4+8],  k2v.x, s2); s2 = fmaf(qr[d4+9],  k2v.y, s2);
                s2 = fmaf(qr[d4+10], k2v.z, s2); s2 = fmaf(qr[d4+11], k2v.w, s2);
                s3 = fmaf(qr[d4+12], k3v.x, s3); s3 = fmaf(qr[d4+13], k3v.y, s3);
                s3 = fmaf(qr[d4+14], k3v.z, s3); s3 = fmaf(qr[d4+15], k3v.w, s3);
            }
            float s = (s0 + s1) + (s2 + s3);

            if (s > mrun) {   // rare: rescale running state
                float corr = __expf(mrun - s);
                lrun *= corr;
                #pragma unroll
                for (int d = 0; d < HD_; d++) acc[d] *= corr;
                mrun = s;
            }
            float p = __expf(s - mrun);
            lrun += p;
            #pragma unroll
            for (int d4 = 0; d4 < HD_; d4 += 4) {
                float4 vv = *reinterpret_cast<const float4*>(&Vs[kk][d4]);
                acc[d4]   = fmaf(p, vv.x, acc[d4]);
                acc[d4+1] = fmaf(p, vv.y, acc[d4+1]);
                acc[d4+2] = fmaf(p, vv.z, acc[d4+2]);
                acc[d4+3] = fmaf(p, vv.w, acc[d4+3]);
            }
        }
    }

    const float inv = __fdividef(1.f, lrun);
    float* orow = g_attn + ((size_t)(b * NQ + q)) * HID_ + h * HD_;
    #pragma unroll
    for (int d4 = 0; d4 < HD_; d4 += 4) {
        float4 o = make_float4(acc[d4] * inv, acc[d4+1] * inv,
                               acc[d4+2] * inv, acc[d4+3] * inv);
        *reinterpret_cast<float4*>(&orow[d4]) = o;
    }
}

// ---------------------------------------------------------------------------
extern "C" void kernel_launch(void* const* d_in, const int* in_sizes, int n_in,
                              void* d_out, int out_size)
{
    const float* q_in      = (const float*)d_in[0];
    const float* kv_in     = (const float*)d_in[1];
    const float* q_coords  = (const float*)d_in[2];
    const float* kv_coords = (const float*)d_in[3];
    const float* Wq        = (const float*)d_in[4];
    const float* Wk        = (const float*)d_in[5];
    const float* Wv        = (const float*)d_in[6];
    const float* Wo        = (const float*)d_in[7];
    const float* W1        = (const float*)d_in[8];
    const float* b1        = (const float*)d_in[9];
    const float* W2        = (const float*)d_in[10];
    const float* b2        = (const float*)d_in[11];
    float* out             = (float*)d_out;

    float *Qp, *Kp, *Vp, *Ap;
    cudaGetSymbolAddress((void**)&Qp, g_Q);
    cudaGetSymbolAddress((void**)&Kp, g_K);
    cudaGetSymbolAddress((void**)&Vp, g_V);
    cudaGetSymbolAddress((void**)&Ap, g_attn);

    // bias LUT pipeline
    init_kernel<<<1, 32>>>();
    norm_kernel<<<(B_ * NQ + B_ * NK + 255) / 256, 256>>>(q_coords, kv_coords);
    lut_kernel<<<(LUT_T + 255) / 256, 256>>>(W1, b1, W2, b2);

    // Projections
    gemm_kernel<<<dim3(HID_ / GBN, (B_ * NQ) / GBM), 256>>>(q_in, Wq, Qp, B_ * NQ, HID_, DIM_);
    gemm_kernel<<<dim3(HID_ / GBN, (B_ * NK) / GBM), 256>>>(kv_in, Wk, Kp, B_ * NK, HID_, DIM_);
    gemm_kernel<<<dim3(HID_ / GBN, (B_ * NK) / GBM), 256>>>(kv_in, Wv, Vp, B_ * NK, HID_, DIM_);

    // Flash attention with LUT bias
    attn_kernel<<<dim3(NQ / QT, H_, B_), QT>>>(q_coords, kv_coords);

    // Output projection
    gemm_kernel<<<dim3(DIM_ / GBN, (B_ * NQ) / GBM), 256>>>(Ap, Wo, out, B_ * NQ, DIM_, HID_);
}

// round 3
// speedup vs baseline: 2.1500x; 2.1500x over previous
#include <cuda_runtime.h>
#include <math.h>

#define B_    2
#define NQ    1024
#define NK    2048
#define DIM_  512
#define HID_  512
#define H_    8
#define HD_   64
#define RBH   64
#define LUT_T 1024

// Static device scratch (no runtime allocation allowed)
__device__ float g_Q[(size_t)B_ * NQ * HID_];
__device__ float g_K[(size_t)B_ * NK * HID_];
__device__ float g_V[(size_t)B_ * NK * HID_];
__device__ float g_attn[(size_t)B_ * NQ * HID_];
__device__ float g_lut[H_ * LUT_T];
__device__ unsigned int g_maxbits[2];
__device__ float g_inv_step;

// ---------------------------------------------------------------------------
// LUT pipeline
// ---------------------------------------------------------------------------
__global__ void init_kernel() {
    if (threadIdx.x < 2) g_maxbits[threadIdx.x] = 0u;
}

__global__ __launch_bounds__(256) void norm_kernel(
    const float* __restrict__ qc, const float* __restrict__ kc)
{
    const int NQT = B_ * NQ;
    const int NKT = B_ * NK;
    int i = blockIdx.x * 256 + threadIdx.x;
    float n = 0.f;
    int which = 0;
    if (i < NQT) {
        float x = qc[i*3], y = qc[i*3+1], z = qc[i*3+2];
        n = sqrtf(fmaf(x,x,fmaf(y,y,z*z)));
    } else if (i < NQT + NKT) {
        int j = i - NQT;
        float x = kc[j*3], y = kc[j*3+1], z = kc[j*3+2];
        n = sqrtf(fmaf(x,x,fmaf(y,y,z*z)));
        which = 1;
    }
    atomicMax(&g_maxbits[which], __float_as_uint(n));
}

__global__ __launch_bounds__(256) void lut_kernel(
    const float* __restrict__ W1, const float* __restrict__ b1,
    const float* __restrict__ W2, const float* __restrict__ b2)
{
    __shared__ float sW1[RBH], sb1[RBH], sW2[RBH * H_];
    int t = threadIdx.x;
    if (t < RBH) { sW1[t] = W1[t]; sb1[t] = b1[t]; }
    for (int i = t; i < RBH * H_; i += 256) sW2[i] = W2[i];
    __syncthreads();

    float dmax = __uint_as_float(g_maxbits[0]) + __uint_as_float(g_maxbits[1]) + 1e-3f;
    float step = dmax / (float)(LUT_T - 1);
    if (blockIdx.x == 0 && t == 0) g_inv_step = 1.0f / step;

    int i = blockIdx.x * 256 + t;
    if (i >= LUT_T) return;
    float d = step * (float)i;

    float o[H_];
    #pragma unroll
    for (int hh = 0; hh < H_; hh++) o[hh] = b2[hh];
    #pragma unroll 8
    for (int j = 0; j < RBH; j++) {
        float x = fmaf(d, sW1[j], sb1[j]);
        float s = __fdividef(x, 1.0f + __expf(-x));
        #pragma unroll
        for (int hh = 0; hh < H_; hh++)
            o[hh] = fmaf(s, sW2[j * H_ + hh], o[hh]);
    }
    #pragma unroll
    for (int hh = 0; hh < H_; hh++) g_lut[hh * LUT_T + i] = o[hh];
}

// ---------------------------------------------------------------------------
// fp32 GEMM body (128x64 tile, BK=16, 256 thr, 8x4 micro, double-buffered)
// ---------------------------------------------------------------------------
#define GBM 128
#define GBN 64
#define GBK 16

__device__ __forceinline__ void gemm_body(
    const float* __restrict__ A, const float* __restrict__ Bm,
    float* __restrict__ C, int M, int N, int K,
    float As[2][GBK][GBM + 4], float Bs[2][GBK][GBN + 4])
{
    const int tid = threadIdx.x;
    const int tx  = tid & 15;
    const int ty  = tid >> 4;
    const int row0 = blockIdx.y * GBM;
    const int col0 = blockIdx.x * GBN;

    const int am = tid >> 1;
    const int av = (tid & 1) * 8;
    const int bk = tid >> 4;
    const int bn = (tid & 15) * 4;

    float acc[8][4] = {};

    float4 a0 = *reinterpret_cast<const float4*>(&A[(size_t)(row0 + am) * K + av]);
    float4 a1 = *reinterpret_cast<const float4*>(&A[(size_t)(row0 + am) * K + av + 4]);
    float4 b0 = *reinterpret_cast<const float4*>(&Bm[(size_t)bk * N + col0 + bn]);
    As[0][av+0][am]=a0.x; As[0][av+1][am]=a0.y; As[0][av+2][am]=a0.z; As[0][av+3][am]=a0.w;
    As[0][av+4][am]=a1.x; As[0][av+5][am]=a1.y; As[0][av+6][am]=a1.z; As[0][av+7][am]=a1.w;
    *reinterpret_cast<float4*>(&Bs[0][bk][bn]) = b0;
    __syncthreads();

    int buf = 0;
    for (int k0 = 0; k0 < K; k0 += GBK) {
        const int nk = k0 + GBK;
        float4 na0, na1, nb0;
        if (nk < K) {
            na0 = *reinterpret_cast<const float4*>(&A[(size_t)(row0 + am) * K + nk + av]);
            na1 = *reinterpret_cast<const float4*>(&A[(size_t)(row0 + am) * K + nk + av + 4]);
            nb0 = *reinterpret_cast<const float4*>(&Bm[(size_t)(nk + bk) * N + col0 + bn]);
        }
        #pragma unroll
        for (int kk = 0; kk < GBK; kk++) {
            float4 A0 = *reinterpret_cast<const float4*>(&As[buf][kk][ty * 8]);
            float4 A1 = *reinterpret_cast<const float4*>(&As[buf][kk][ty * 8 + 4]);
            float4 B0 = *reinterpret_cast<const float4*>(&Bs[buf][kk][tx * 4]);
            float av8[8] = {A0.x,A0.y,A0.z,A0.w,A1.x,A1.y,A1.z,A1.w};
            float bv[4]  = {B0.x,B0.y,B0.z,B0.w};
            #pragma unroll
            for (int i = 0; i < 8; i++)
                #pragma unroll
                for (int j = 0; j < 4; j++)
                    acc[i][j] = fmaf(av8[i], bv[j], acc[i][j]);
        }
        if (nk < K) {
            int nb = buf ^ 1;
            As[nb][av+0][am]=na0.x; As[nb][av+1][am]=na0.y; As[nb][av+2][am]=na0.z; As[nb][av+3][am]=na0.w;
            As[nb][av+4][am]=na1.x; As[nb][av+5][am]=na1.y; As[nb][av+6][am]=na1.z; As[nb][av+7][am]=na1.w;
            *reinterpret_cast<float4*>(&Bs[nb][bk][bn]) = nb0;
            __syncthreads();
            buf = nb;
        }
    }

    #pragma unroll
    for (int i = 0; i < 8; i++) {
        float4 o = make_float4(acc[i][0], acc[i][1], acc[i][2], acc[i][3]);
        *reinterpret_cast<float4*>(
            &C[(size_t)(row0 + ty * 8 + i) * N + col0 + tx * 4]) = o;
    }
}

__global__ __launch_bounds__(256) void gemm_kernel(
    const float* __restrict__ A, const float* __restrict__ Bm,
    float* __restrict__ C, int M, int N, int K)
{
    __shared__ float As[2][GBK][GBM + 4];
    __shared__ float Bs[2][GBK][GBN + 4];
    gemm_body(A, Bm, C, M, N, K, As, Bs);
}

// K and V projections fused via blockIdx.z
__global__ __launch_bounds__(256) void gemm_dual_kernel(
    const float* __restrict__ A,
    const float* __restrict__ B0, const float* __restrict__ B1,
    float* __restrict__ C0, float* __restrict__ C1, int M, int N, int K)
{
    __shared__ float As[2][GBK][GBM + 4];
    __shared__ float Bs[2][GBK][GBN + 4];
    gemm_body(A, blockIdx.z ? B1 : B0, blockIdx.z ? C1 : C0, M, N, K, As, Bs);
}

// ---------------------------------------------------------------------------
// Flash attention as two register-blocked GEMMs + online softmax.
// CTA: 64 q-rows x full HD. 256 threads, 4x4 micro-tiles. Dynamic SMEM.
// ---------------------------------------------------------------------------
#define AQ 64
#define AK 64
// float offsets into dynamic smem
#define OFF_QS   0                 // [64][68]  Q^T (dim-major)
#define OFF_KS   4352              // [64][68]  K^T (dim-major)
#define OFF_VS   8704              // [64][64]  V (k-major)
#define OFF_PS   12800             // [64][68]  P (row-major)
#define OFF_LUT  17152             // [1024]
#define OFF_KC   18176             // [192]
#define ATT_SMEM_FLOATS 18368

__global__ __launch_bounds__(256, 2) void attn_kernel(
    const float* __restrict__ qc, const float* __restrict__ kc)
{
    extern __shared__ float sm[];
    float* Qs   = sm + OFF_QS;
    float* Ks   = sm + OFF_KS;
    float* Vs   = sm + OFF_VS;
    float* Ps   = sm + OFF_PS;
    float* slut = sm + OFF_LUT;
    float* skc  = sm + OFF_KC;

    const int b  = blockIdx.z;
    const int h  = blockIdx.y;
    const int q0 = blockIdx.x * AQ;
    const int tid = threadIdx.x;
    const int tx = tid & 15;
    const int ty = tid >> 4;

    // stage LUT
    for (int i = tid; i < LUT_T; i += 256) slut[i] = g_lut[h * LUT_T + i];
    const float inv_step = g_inv_step;

    // load Q tile (scale folded), transposed: Qs[d][row]
    {
        const int row = tid >> 2;
        const int v   = tid & 3;
        const float* qp = g_Q + ((size_t)(b * NQ + q0 + row)) * HID_ + h * HD_ + v * 16;
        #pragma unroll
        for (int u = 0; u < 4; u++) {
            float4 t = *reinterpret_cast<const float4*>(qp + u * 4);
            int d = v * 16 + u * 4;
            Qs[(d+0)*68 + row] = t.x * 0.125f;
            Qs[(d+1)*68 + row] = t.y * 0.125f;
            Qs[(d+2)*68 + row] = t.z * 0.125f;
            Qs[(d+3)*68 + row] = t.w * 0.125f;
        }
    }

    // per-row q coords
    float qcr[4][3];
    #pragma unroll
    for (int i = 0; i < 4; i++) {
        const float* p = qc + ((size_t)b * NQ + q0 + ty * 4 + i) * 3;
        qcr[i][0] = p[0]; qcr[i][1] = p[1]; qcr[i][2] = p[2];
    }

    float o[4][4] = {};
    float mrun[4], lrun[4];
    #pragma unroll
    for (int i = 0; i < 4; i++) { mrun[i] = -INFINITY; lrun[i] = 0.f; }

    const float* Kp  = g_K + ((size_t)b * NK) * HID_ + h * HD_;
    const float* Vp  = g_V + ((size_t)b * NK) * HID_ + h * HD_;
    const float* kcb = kc + (size_t)b * NK * 3;

    for (int k0 = 0; k0 < NK; k0 += AK) {
        __syncthreads();   // prev GEMM2 done with Ps/Vs
        // load K (transposed) and V tiles
        {
            const int kr = tid >> 2;
            const int v  = tid & 3;
            const float* kp = Kp + (size_t)(k0 + kr) * HID_ + v * 16;
            const float* vp = Vp + (size_t)(k0 + kr) * HID_ + v * 16;
            #pragma unroll
            for (int u = 0; u < 4; u++) {
                int d = v * 16 + u * 4;
                float4 t = *reinterpret_cast<const float4*>(kp + u * 4);
                Ks[(d+0)*68 + kr] = t.x;
                Ks[(d+1)*68 + kr] = t.y;
                Ks[(d+2)*68 + kr] = t.z;
                Ks[(d+3)*68 + kr] = t.w;
                float4 tv = *reinterpret_cast<const float4*>(vp + u * 4);
                *reinterpret_cast<float4*>(&Vs[kr * 64 + d]) = tv;
            }
        }
        if (tid < AK * 3) skc[tid] = kcb[(size_t)k0 * 3 + tid];
        __syncthreads();

        // GEMM1: S = Q K^T
        float s[4][4] = {};
        #pragma unroll 8
        for (int kk = 0; kk < HD_; kk++) {
            float4 a4 = *reinterpret_cast<const float4*>(&Qs[kk * 68 + ty * 4]);
            float4 b4 = *reinterpret_cast<const float4*>(&Ks[kk * 68 + tx * 4]);
            float av[4] = {a4.x, a4.y, a4.z, a4.w};
            float bv[4] = {b4.x, b4.y, b4.z, b4.w};
            #pragma unroll
            for (int i = 0; i < 4; i++)
                #pragma unroll
                for (int j = 0; j < 4; j++)
                    s[i][j] = fmaf(av[i], bv[j], s[i][j]);
        }

        // bias + online softmax (row state replicated across 16 tx lanes)
        #pragma unroll
        for (int i = 0; i < 4; i++) {
            float rm = -INFINITY;
            #pragma unroll
            for (int j = 0; j < 4; j++) {
                int c = tx * 4 + j;
                float dx = qcr[i][0] - skc[3*c+0];
                float dy = qcr[i][1] - skc[3*c+1];
                float dz = qcr[i][2] - skc[3*c+2];
                float dd = sqrtf(fmaf(dx, dx, fmaf(dy, dy, dz * dz)));
                float t  = dd * inv_step;
                int   ii = (int)t;
                ii = (ii > LUT_T - 2) ? (LUT_T - 2) : ii;
                float fr = t - (float)ii;
                float lo = slut[ii], hi = slut[ii + 1];
                s[i][j] += fmaf(fr, hi - lo, lo);
                rm = fmaxf(rm, s[i][j]);
            }
            rm = fmaxf(rm, __shfl_xor_sync(0xffffffffu, rm, 1));
            rm = fmaxf(rm, __shfl_xor_sync(0xffffffffu, rm, 2));
            rm = fmaxf(rm, __shfl_xor_sync(0xffffffffu, rm, 4));
            rm = fmaxf(rm, __shfl_xor_sync(0xffffffffu, rm, 8));
            float mnew  = fmaxf(mrun[i], rm);
            float alpha = __expf(mrun[i] - mnew);
            mrun[i] = mnew;
            float ps = 0.f;
            #pragma unroll
            for (int j = 0; j < 4; j++) {
                float p = __expf(s[i][j] - mnew);
                Ps[(ty * 4 + i) * 68 + tx * 4 + j] = p;
                ps += p;
            }
            ps += __shfl_xor_sync(0xffffffffu, ps, 1);
            ps += __shfl_xor_sync(0xffffffffu, ps, 2);
            ps += __shfl_xor_sync(0xffffffffu, ps, 4);
            ps += __shfl_xor_sync(0xffffffffu, ps, 8);
            lrun[i] = lrun[i] * alpha + ps;
            #pragma unroll
            for (int j = 0; j < 4; j++) o[i][j] *= alpha;
        }
        __syncthreads();

        // GEMM2: O += P V
        #pragma unroll 8
        for (int kk = 0; kk < AK; kk++) {
            float a[4];
            #pragma unroll
            for (int i = 0; i < 4; i++) a[i] = Ps[(ty * 4 + i) * 68 + kk];
            float4 b4 = *reinterpret_cast<const float4*>(&Vs[kk * 64 + tx * 4]);
            float bv[4] = {b4.x, b4.y, b4.z, b4.w};
            #pragma unroll
            for (int i = 0; i < 4; i++)
                #pragma unroll
                for (int j = 0; j < 4; j++)
                    o[i][j] = fmaf(a[i], bv[j], o[i][j]);
        }
    }

    // epilogue
    #pragma unroll
    for (int i = 0; i < 4; i++) {
        float inv = __fdividef(1.f, lrun[i]);
        float4 w = make_float4(o[i][0]*inv, o[i][1]*inv, o[i][2]*inv, o[i][3]*inv);
        *reinterpret_cast<float4*>(
            &g_attn[((size_t)(b * NQ + q0 + ty * 4 + i)) * HID_ + h * HD_ + tx * 4]) = w;
    }
}

// ---------------------------------------------------------------------------
extern "C" void kernel_launch(void* const* d_in, const int* in_sizes, int n_in,
                              void* d_out, int out_size)
{
    const float* q_in      = (const float*)d_in[0];
    const float* kv_in     = (const float*)d_in[1];
    const float* q_coords  = (const float*)d_in[2];
    const float* kv_coords = (const float*)d_in[3];
    const float* Wq        = (const float*)d_in[4];
    const float* Wk        = (const float*)d_in[5];
    const float* Wv        = (const float*)d_in[6];
    const float* Wo        = (const float*)d_in[7];
    const float* W1        = (const float*)d_in[8];
    const float* b1        = (const float*)d_in[9];
    const float* W2        = (const float*)d_in[10];
    const float* b2        = (const float*)d_in[11];
    float* out             = (float*)d_out;

    float *Qp, *Kp, *Vp, *Ap;
    cudaGetSymbolAddress((void**)&Qp, g_Q);
    cudaGetSymbolAddress((void**)&Kp, g_K);
    cudaGetSymbolAddress((void**)&Vp, g_V);
    cudaGetSymbolAddress((void**)&Ap, g_attn);

    static bool attr_set = false;
    if (!attr_set) {
        cudaFuncSetAttribute(attn_kernel,
            cudaFuncAttributeMaxDynamicSharedMemorySize, ATT_SMEM_FLOATS * 4);
        attr_set = true;
    }

    // bias LUT pipeline
    init_kernel<<<1, 32>>>();
    norm_kernel<<<(B_ * NQ + B_ * NK + 255) / 256, 256>>>(q_coords, kv_coords);
    lut_kernel<<<(LUT_T + 255) / 256, 256>>>(W1, b1, W2, b2);

    // Projections
    gemm_kernel<<<dim3(HID_ / GBN, (B_ * NQ) / GBM), 256>>>(q_in, Wq, Qp, B_ * NQ, HID_, DIM_);
    gemm_dual_kernel<<<dim3(HID_ / GBN, (B_ * NK) / GBM, 2), 256>>>(
        kv_in, Wk, Wv, Kp, Vp, B_ * NK, HID_, DIM_);

    // Flash attention (GEMM-style) with LUT bias
    attn_kernel<<<dim3(NQ / AQ, H_, B_), 256, ATT_SMEM_FLOATS * 4>>>(q_coords, kv_coords);

    // Output projection
    gemm_kernel<<<dim3(DIM_ / GBN, (B_ * NQ) / GBM), 256>>>(Ap, Wo, out, B_ * NQ, DIM_, HID_);
}

// round 4
// speedup vs baseline: 4.2031x; 1.9549x over previous
#include <cuda_runtime.h>
#include <math.h>
#include <stdint.h>

#define B_    2
#define NQ    1024
#define NK    2048
#define DIM_  512
#define HID_  512
#define H_    8
#define HD_   64
#define RBH   64
#define LUT_T 2048

// Static device scratch (no runtime allocation allowed)
__device__ float g_Q[(size_t)B_ * NQ * HID_];
__device__ float g_K[(size_t)B_ * NK * HID_];
__device__ float g_V[(size_t)B_ * NK * HID_];
__device__ float g_attn[(size_t)B_ * NQ * HID_];
__device__ float g_lut[H_ * LUT_T];
__device__ unsigned int g_maxbits[2];
__device__ float g_inv_step2;   // 1 / (d^2 LUT step)

// ---------------------------------------------------------------------------
// TF32 helpers
// ---------------------------------------------------------------------------
__device__ __forceinline__ uint32_t f2tf(float x) {
    uint32_t r; asm("cvt.rna.tf32.f32 %0, %1;" : "=r"(r) : "f"(x)); return r;
}
__device__ __forceinline__ void mma8(float* d, const uint32_t* a, uint32_t b0, uint32_t b1) {
    asm volatile(
        "mma.sync.aligned.m16n8k8.row.col.f32.tf32.tf32.f32 "
        "{%0,%1,%2,%3}, {%4,%5,%6,%7}, {%8,%9}, {%0,%1,%2,%3};"
        : "+f"(d[0]), "+f"(d[1]), "+f"(d[2]), "+f"(d[3])
        : "r"(a[0]), "r"(a[1]), "r"(a[2]), "r"(a[3]), "r"(b0), "r"(b1));
}

// ---------------------------------------------------------------------------
// LUT pipeline (bias as function of squared distance)
// ---------------------------------------------------------------------------
__global__ void init_kernel() {
    if (threadIdx.x < 2) g_maxbits[threadIdx.x] = 0u;
}

__global__ __launch_bounds__(256) void norm_kernel(
    const float* __restrict__ qc, const float* __restrict__ kc)
{
    const int NQT = B_ * NQ;
    const int NKT = B_ * NK;
    int i = blockIdx.x * 256 + threadIdx.x;
    float n = 0.f;
    int which = 0;
    if (i < NQT) {
        float x = qc[i*3], y = qc[i*3+1], z = qc[i*3+2];
        n = sqrtf(fmaf(x,x,fmaf(y,y,z*z)));
    } else if (i < NQT + NKT) {
        int j = i - NQT;
        float x = kc[j*3], y = kc[j*3+1], z = kc[j*3+2];
        n = sqrtf(fmaf(x,x,fmaf(y,y,z*z)));
        which = 1;
    }
    atomicMax(&g_maxbits[which], __float_as_uint(n));
}

__global__ __launch_bounds__(256) void lut_kernel(
    const float* __restrict__ W1, const float* __restrict__ b1,
    const float* __restrict__ W2, const float* __restrict__ b2)
{
    __shared__ float sW1[RBH], sb1[RBH], sW2[RBH * H_];
    int t = threadIdx.x;
    if (t < RBH) { sW1[t] = W1[t]; sb1[t] = b1[t]; }
    for (int i = t; i < RBH * H_; i += 256) sW2[i] = W2[i];
    __syncthreads();

    float dmax = __uint_as_float(g_maxbits[0]) + __uint_as_float(g_maxbits[1]) + 1e-3f;
    float step2 = dmax * dmax / (float)(LUT_T - 1);
    if (blockIdx.x == 0 && t == 0) g_inv_step2 = 1.0f / step2;

    int i = blockIdx.x * 256 + t;
    if (i >= LUT_T) return;
    float d = sqrtf(step2 * (float)i);

    float o[H_];
    #pragma unroll
    for (int hh = 0; hh < H_; hh++) o[hh] = b2[hh];
    #pragma unroll 8
    for (int j = 0; j < RBH; j++) {
        float x = fmaf(d, sW1[j], sb1[j]);
        float s = __fdividef(x, 1.0f + __expf(-x));
        #pragma unroll
        for (int hh = 0; hh < H_; hh++)
            o[hh] = fmaf(s, sW2[j * H_ + hh], o[hh]);
    }
    #pragma unroll
    for (int hh = 0; hh < H_; hh++) g_lut[hh * LUT_T + i] = o[hh];
}

// ---------------------------------------------------------------------------
// TF32 tensor-core GEMM: C[M,N] = A[M,K] @ B[K,N]. 128x64x16 tile, 256 thr,
// 8 warps (4m x 2n), warp tile 32x32 (2 m-frags x 4 n-frags), double-buffered.
// ---------------------------------------------------------------------------
#define AS_STR 20
#define BS_STR 72

__device__ __forceinline__ void gemm_tf32_body(
    const float* __restrict__ A, const float* __restrict__ Bm,
    float* __restrict__ C, int M, int N, int K,
    uint32_t* As, uint32_t* Bs)   // As: 2*128*20, Bs: 2*16*72
{
    const int tid  = threadIdx.x;
    const int lane = tid & 31;
    const int wid  = tid >> 5;
    const int wm   = (wid >> 1) * 32;
    const int wn   = (wid & 1) * 32;
    const int row0 = blockIdx.y * 128;
    const int col0 = blockIdx.x * 64;
    const int lq   = lane >> 2;     // 0..7
    const int lr   = lane & 3;      // 0..3

    const int ar = tid >> 1, ac = (tid & 1) * 8;
    const int bk = tid >> 4, bn = (tid & 15) * 4;

    float acc[2][4][4] = {};

    // preload tile 0
    {
        float4 a0 = *(const float4*)&A[(size_t)(row0 + ar) * K + ac];
        float4 a1 = *(const float4*)&A[(size_t)(row0 + ar) * K + ac + 4];
        float4 b0 = *(const float4*)&Bm[(size_t)bk * N + col0 + bn];
        *(uint4*)&As[ar * AS_STR + ac]     = make_uint4(f2tf(a0.x), f2tf(a0.y), f2tf(a0.z), f2tf(a0.w));
        *(uint4*)&As[ar * AS_STR + ac + 4] = make_uint4(f2tf(a1.x), f2tf(a1.y), f2tf(a1.z), f2tf(a1.w));
        *(uint4*)&Bs[bk * BS_STR + bn]     = make_uint4(f2tf(b0.x), f2tf(b0.y), f2tf(b0.z), f2tf(b0.w));
    }
    __syncthreads();

    int buf = 0;
    for (int k0 = 0; k0 < K; k0 += 16) {
        const bool more = (k0 + 16) < K;
        float4 na0, na1, nb0;
        if (more) {
            na0 = *(const float4*)&A[(size_t)(row0 + ar) * K + k0 + 16 + ac];
            na1 = *(const float4*)&A[(size_t)(row0 + ar) * K + k0 + 16 + ac + 4];
            nb0 = *(const float4*)&Bm[(size_t)(k0 + 16 + bk) * N + col0 + bn];
        }
        const uint32_t* Ab = As + buf * (128 * AS_STR);
        const uint32_t* Bb = Bs + buf * (16 * BS_STR);

        #pragma unroll
        for (int s = 0; s < 2; s++) {
            uint32_t af[2][4], bf[4][2];
            const int kc_ = s * 8 + lr;
            #pragma unroll
            for (int mf = 0; mf < 2; mf++) {
                const int r = wm + mf * 16 + lq;
                af[mf][0] = Ab[r * AS_STR + kc_];
                af[mf][1] = Ab[(r + 8) * AS_STR + kc_];
                af[mf][2] = Ab[r * AS_STR + kc_ + 4];
                af[mf][3] = Ab[(r + 8) * AS_STR + kc_ + 4];
            }
            #pragma unroll
            for (int nf = 0; nf < 4; nf++) {
                const int cc = wn + nf * 8 + lq;
                bf[nf][0] = Bb[kc_ * BS_STR + cc];
                bf[nf][1] = Bb[(kc_ + 4) * BS_STR + cc];
            }
            #pragma unroll
            for (int mf = 0; mf < 2; mf++)
                #pragma unroll
                for (int nf = 0; nf < 4; nf++)
                    mma8(acc[mf][nf], af[mf], bf[nf][0], bf[nf][1]);
        }

        if (more) {
            buf ^= 1;
            uint32_t* Aw = As + buf * (128 * AS_STR);
            uint32_t* Bw = Bs + buf * (16 * BS_STR);
            *(uint4*)&Aw[ar * AS_STR + ac]     = make_uint4(f2tf(na0.x), f2tf(na0.y), f2tf(na0.z), f2tf(na0.w));
            *(uint4*)&Aw[ar * AS_STR + ac + 4] = make_uint4(f2tf(na1.x), f2tf(na1.y), f2tf(na1.z), f2tf(na1.w));
            *(uint4*)&Bw[bk * BS_STR + bn]     = make_uint4(f2tf(nb0.x), f2tf(nb0.y), f2tf(nb0.z), f2tf(nb0.w));
            __syncthreads();
        }
    }

    #pragma unroll
    for (int mf = 0; mf < 2; mf++)
        #pragma unroll
        for (int nf = 0; nf < 4; nf++) {
            const int r = row0 + wm + mf * 16 + lq;
            const int c = col0 + wn + nf * 8 + 2 * lr;
            *(float2*)&C[(size_t)r * N + c]       = make_float2(acc[mf][nf][0], acc[mf][nf][1]);
            *(float2*)&C[(size_t)(r + 8) * N + c] = make_float2(acc[mf][nf][2], acc[mf][nf][3]);
        }
}

__global__ __launch_bounds__(256) void gemm_kernel(
    const float* __restrict__ A, const float* __restrict__ Bm,
    float* __restrict__ C, int M, int N, int K)
{
    __shared__ uint32_t As[2 * 128 * AS_STR];
    __shared__ uint32_t Bs[2 * 16 * BS_STR];
    gemm_tf32_body(A, Bm, C, M, N, K, As, Bs);
}

__global__ __launch_bounds__(256) void gemm_dual_kernel(
    const float* __restrict__ A,
    const float* __restrict__ B0, const float* __restrict__ B1,
    float* __restrict__ C0, float* __restrict__ C1, int M, int N, int K)
{
    __shared__ uint32_t As[2 * 128 * AS_STR];
    __shared__ uint32_t Bs[2 * 16 * BS_STR];
    gemm_tf32_body(A, blockIdx.z ? B1 : B0, blockIdx.z ? C1 : C0, M, N, K, As, Bs);
}

// ---------------------------------------------------------------------------
// TF32 flash attention. CTA = 128 q x 64 k, 256 thr / 8 warps,
// warp owns 16 q rows. Q frags in registers. K/V double-buffered smem.
// ---------------------------------------------------------------------------
#define KV_STR 76
#define P_STR  68
// uint offsets into dynamic smem
#define OFF_K   0                       // 2 * 64 * 76 = 9728
#define OFF_V   9728                    // 9728
#define OFF_P   19456                   // 128 * 68 = 8704
#define OFF_LUT 28160                   // 2048
#define OFF_KC  30208                   // 2 * 192 = 384
#define ATT_SMEM_U32 30592              // * 4 = 122368 B

__global__ __launch_bounds__(256) void attn_kernel(
    const float* __restrict__ qc, const float* __restrict__ kc)
{
    extern __shared__ uint32_t sm[];
    uint32_t* Kn   = sm + OFF_K;
    uint32_t* Vn   = sm + OFF_V;
    uint32_t* Ps   = sm + OFF_P;
    float*    slut = (float*)(sm + OFF_LUT);
    float*    skc  = (float*)(sm + OFF_KC);

    const int b   = blockIdx.z;
    const int h   = blockIdx.y;
    const int q0  = blockIdx.x * 128;
    const int tid = threadIdx.x;
    const int lane = tid & 31;
    const int w    = tid >> 5;
    const int lq   = lane >> 2;   // 0..7
    const int lr   = lane & 3;    // 0..3

    // stage LUT
    for (int i = tid; i < LUT_T; i += 256) slut[i] = g_lut[h * LUT_T + i];
    const float inv_step2 = g_inv_step2;

    // Q fragments in registers (scale folded)
    uint32_t qa[8][4];
    {
        const size_t r0 = ((size_t)(b * NQ + q0 + w * 16 + lq)) * HID_ + h * HD_;
        const size_t r1 = r0 + 8 * HID_;
        #pragma unroll
        for (int ks = 0; ks < 8; ks++) {
            qa[ks][0] = f2tf(0.125f * g_Q[r0 + ks * 8 + lr]);
            qa[ks][1] = f2tf(0.125f * g_Q[r1 + ks * 8 + lr]);
            qa[ks][2] = f2tf(0.125f * g_Q[r0 + ks * 8 + lr + 4]);
            qa[ks][3] = f2tf(0.125f * g_Q[r1 + ks * 8 + lr + 4]);
        }
    }
    // per-thread q coords for its two rows
    float q0x, q0y, q0z, q1x, q1y, q1z;
    {
        const float* p0 = qc + ((size_t)b * NQ + q0 + w * 16 + lq) * 3;
        const float* p1 = p0 + 8 * 3;
        q0x = p0[0]; q0y = p0[1]; q0z = p0[2];
        q1x = p1[0]; q1y = p1[1]; q1z = p1[2];
    }

    float of[8][4] = {};
    float m0 = -INFINITY, m1 = -INFINITY, l0 = 0.f, l1 = 0.f;

    const float* Kp  = g_K + ((size_t)b * NK) * HID_ + h * HD_;
    const float* Vp  = g_V + ((size_t)b * NK) * HID_ + h * HD_;
    const float* kcb = kc + (size_t)b * NK * 3;

    // loader indices: key = tid>>2 (0..63), dbase = (tid&3)*16
    const int lkey = tid >> 2;
    const int ldb  = (tid & 3) * 16;

    // prologue: stage tile 0
    {
        #pragma unroll
        for (int u = 0; u < 4; u++) {
            float4 kv = *(const float4*)&Kp[(size_t)lkey * HID_ + ldb + u * 4];
            float4 vv = *(const float4*)&Vp[(size_t)lkey * HID_ + ldb + u * 4];
            *(uint4*)&Kn[lkey * KV_STR + ldb + u * 4] =
                make_uint4(f2tf(kv.x), f2tf(kv.y), f2tf(kv.z), f2tf(kv.w));
            *(uint4*)&Vn[lkey * KV_STR + ldb + u * 4] =
                make_uint4(f2tf(vv.x), f2tf(vv.y), f2tf(vv.z), f2tf(vv.w));
        }
        if (tid < 192) skc[tid] = kcb[tid];
    }
    __syncthreads();

    const int NT = NK / 64;
    int buf = 0;
    for (int t = 0; t < NT; t++) {
        const bool more = (t + 1) < NT;
        float4 nk[4], nv[4];
        float nkc = 0.f;
        if (more) {
            const size_t kb = (size_t)((t + 1) * 64 + lkey) * HID_;
            #pragma unroll
            for (int u = 0; u < 4; u++) {
                nk[u] = *(const float4*)&Kp[kb + ldb + u * 4];
                nv[u] = *(const float4*)&Vp[kb + ldb + u * 4];
            }
            if (tid < 192) nkc = kcb[(size_t)(t + 1) * 192 + tid];
        }

        const uint32_t* Kb = Kn + buf * (64 * KV_STR);
        const uint32_t* Vb = Vn + buf * (64 * KV_STR);
        const float*    kcs = skc + buf * 192;

        // ---- QK^T ----
        float sacc[8][4] = {};
        #pragma unroll
        for (int ks = 0; ks < 8; ks++) {
            const int dcol = ks * 8 + lr;
            #pragma unroll
            for (int nf = 0; nf < 8; nf++) {
                const int key = nf * 8 + lq;
                uint32_t b0 = Kb[key * KV_STR + dcol];
                uint32_t b1 = Kb[key * KV_STR + dcol + 4];
                mma8(sacc[nf], qa[ks], b0, b1);
            }
        }

        // ---- bias + online softmax ----
        float rm0 = -INFINITY, rm1 = -INFINITY;
        #pragma unroll
        for (int nf = 0; nf < 8; nf++) {
            const int c0 = nf * 8 + 2 * lr;
            float kx0 = kcs[c0*3+0], ky0 = kcs[c0*3+1], kz0 = kcs[c0*3+2];
            float kx1 = kcs[c0*3+3], ky1 = kcs[c0*3+4], kz1 = kcs[c0*3+5];
            {
                float dx = q0x-kx0, dy = q0y-ky0, dz = q0z-kz0;
                float u = fmaf(dx,dx,fmaf(dy,dy,dz*dz)) * inv_step2;
                int ii = (int)u; ii = (ii > LUT_T-2) ? LUT_T-2 : ii;
                float fr = u - (float)ii;
                sacc[nf][0] += fmaf(fr, slut[ii+1]-slut[ii], slut[ii]);
            }
            {
                float dx = q0x-kx1, dy = q0y-ky1, dz = q0z-kz1;
                float u = fmaf(dx,dx,fmaf(dy,dy,dz*dz)) * inv_step2;
                int ii = (int)u; ii = (ii > LUT_T-2) ? LUT_T-2 : ii;
                float fr = u - (float)ii;
                sacc[nf][1] += fmaf(fr, slut[ii+1]-slut[ii], slut[ii]);
            }
            {
                float dx = q1x-kx0, dy = q1y-ky0, dz = q1z-kz0;
                float u = fmaf(dx,dx,fmaf(dy,dy,dz*dz)) * inv_step2;
                int ii = (int)u; ii = (ii > LUT_T-2) ? LUT_T-2 : ii;
                float fr = u - (float)ii;
                sacc[nf][2] += fmaf(fr, slut[ii+1]-slut[ii], slut[ii]);
            }
            {
                float dx = q1x-kx1, dy = q1y-ky1, dz = q1z-kz1;
                float u = fmaf(dx,dx,fmaf(dy,dy,dz*dz)) * inv_step2;
                int ii = (int)u; ii = (ii > LUT_T-2) ? LUT_T-2 : ii;
                float fr = u - (float)ii;
                sacc[nf][3] += fmaf(fr, slut[ii+1]-slut[ii], slut[ii]);
            }
            rm0 = fmaxf(rm0, fmaxf(sacc[nf][0], sacc[nf][1]));
            rm1 = fmaxf(rm1, fmaxf(sacc[nf][2], sacc[nf][3]));
        }
        rm0 = fmaxf(rm0, __shfl_xor_sync(0xffffffffu, rm0, 1));
        rm0 = fmaxf(rm0, __shfl_xor_sync(0xffffffffu, rm0, 2));
        rm1 = fmaxf(rm1, __shfl_xor_sync(0xffffffffu, rm1, 1));
        rm1 = fmaxf(rm1, __shfl_xor_sync(0xffffffffu, rm1, 2));

        const float mn0 = fmaxf(m0, rm0), mn1 = fmaxf(m1, rm1);
        const float a0 = __expf(m0 - mn0), a1 = __expf(m1 - mn1);
        m0 = mn0; m1 = mn1;

        float ps0 = 0.f, ps1 = 0.f;
        const int prow0 = (w * 16 + lq) * P_STR;
        const int prow1 = prow0 + 8 * P_STR;
        #pragma unroll
        for (int nf = 0; nf < 8; nf++) {
            const int c0 = nf * 8 + 2 * lr;
            float p00 = __expf(sacc[nf][0] - mn0);
            float p01 = __expf(sacc[nf][1] - mn0);
            float p10 = __expf(sacc[nf][2] - mn1);
            float p11 = __expf(sacc[nf][3] - mn1);
            ps0 += p00 + p01;
            ps1 += p10 + p11;
            Ps[prow0 + c0]     = f2tf(p00);
            Ps[prow0 + c0 + 1] = f2tf(p01);
            Ps[prow1 + c0]     = f2tf(p10);
            Ps[prow1 + c0 + 1] = f2tf(p11);
        }
        ps0 += __shfl_xor_sync(0xffffffffu, ps0, 1);
        ps0 += __shfl_xor_sync(0xffffffffu, ps0, 2);
        ps1 += __shfl_xor_sync(0xffffffffu, ps1, 1);
        ps1 += __shfl_xor_sync(0xffffffffu, ps1, 2);
        l0 = l0 * a0 + ps0;
        l1 = l1 * a1 + ps1;
        #pragma unroll
        for (int nf = 0; nf < 8; nf++) {
            of[nf][0] *= a0; of[nf][1] *= a0;
            of[nf][2] *= a1; of[nf][3] *= a1;
        }
        __syncwarp();

        // ---- P V ----
        #pragma unroll
        for (int kst = 0; kst < 8; kst++) {
            uint32_t pa[4];
            const int pc = kst * 8 + lr;
            pa[0] = Ps[(w * 16 + lq) * P_STR + pc];
            pa[1] = Ps[(w * 16 + lq + 8) * P_STR + pc];
            pa[2] = Ps[(w * 16 + lq) * P_STR + pc + 4];
            pa[3] = Ps[(w * 16 + lq + 8) * P_STR + pc + 4];
            #pragma unroll
            for (int nf = 0; nf < 8; nf++) {
                const int dcol = nf * 8 + lq;
                uint32_t b0 = Vb[(kst * 8 + lr) * KV_STR + dcol];
                uint32_t b1 = Vb[(kst * 8 + lr + 4) * KV_STR + dcol];
                mma8(of[nf], pa, b0, b1);
            }
        }

        if (more) {
            buf ^= 1;
            uint32_t* Kw = Kn + buf * (64 * KV_STR);
            uint32_t* Vw = Vn + buf * (64 * KV_STR);
            #pragma unroll
            for (int u = 0; u < 4; u++) {
                *(uint4*)&Kw[lkey * KV_STR + ldb + u * 4] =
                    make_uint4(f2tf(nk[u].x), f2tf(nk[u].y), f2tf(nk[u].z), f2tf(nk[u].w));
                *(uint4*)&Vw[lkey * KV_STR + ldb + u * 4] =
                    make_uint4(f2tf(nv[u].x), f2tf(nv[u].y), f2tf(nv[u].z), f2tf(nv[u].w));
            }
            if (tid < 192) skc[buf * 192 + tid] = nkc;
            __syncthreads();
        }
    }

    // epilogue
    const float i0 = __fdividef(1.f, l0);
    const float i1 = __fdividef(1.f, l1);
    const size_t r0 = ((size_t)(b * NQ + q0 + w * 16 + lq)) * HID_ + h * HD_;
    const size_t r1 = r0 + 8 * HID_;
    #pragma unroll
    for (int nf = 0; nf < 8; nf++) {
        const int c = nf * 8 + 2 * lr;
        *(float2*)&g_attn[r0 + c] = make_float2(of[nf][0] * i0, of[nf][1] * i0);
        *(float2*)&g_attn[r1 + c] = make_float2(of[nf][2] * i1, of[nf][3] * i1);
    }
}

// ---------------------------------------------------------------------------
extern "C" void kernel_launch(void* const* d_in, const int* in_sizes, int n_in,
                              void* d_out, int out_size)
{
    const float* q_in      = (const float*)d_in[0];
    const float* kv_in     = (const float*)d_in[1];
    const float* q_coords  = (const float*)d_in[2];
    const float* kv_coords = (const float*)d_in[3];
    const float* Wq        = (const float*)d_in[4];
    const float* Wk        = (const float*)d_in[5];
    const float* Wv        = (const float*)d_in[6];
    const float* Wo        = (const float*)d_in[7];
    const float* W1        = (const float*)d_in[8];
    const float* b1        = (const float*)d_in[9];
    const float* W2        = (const float*)d_in[10];
    const float* b2        = (const float*)d_in[11];
    float* out             = (float*)d_out;

    float *Qp, *Kp, *Vp, *Ap;
    cudaGetSymbolAddress((void**)&Qp, g_Q);
    cudaGetSymbolAddress((void**)&Kp, g_K);
    cudaGetSymbolAddress((void**)&Vp, g_V);
    cudaGetSymbolAddress((void**)&Ap, g_attn);

    static bool attr_set = false;
    if (!attr_set) {
        cudaFuncSetAttribute(attn_kernel,
            cudaFuncAttributeMaxDynamicSharedMemorySize, ATT_SMEM_U32 * 4);
        attr_set = true;
    }

    // bias LUT pipeline
    init_kernel<<<1, 32>>>();
    norm_kernel<<<(B_ * NQ + B_ * NK + 255) / 256, 256>>>(q_coords, kv_coords);
    lut_kernel<<<(LUT_T + 255) / 256, 256>>>(W1, b1, W2, b2);

    // Projections (TF32 tensor cores)
    gemm_kernel<<<dim3(HID_ / 64, (B_ * NQ) / 128), 256>>>(q_in, Wq, Qp, B_ * NQ, HID_, DIM_);
    gemm_dual_kernel<<<dim3(HID_ / 64, (B_ * NK) / 128, 2), 256>>>(
        kv_in, Wk, Wv, Kp, Vp, B_ * NK, HID_, DIM_);

    // Flash attention (TF32 tensor cores) with LUT bias
    attn_kernel<<<dim3(NQ / 128, H_, B_), 256, ATT_SMEM_U32 * 4>>>(q_coords, kv_coords);

    // Output projection
    gemm_kernel<<<dim3(DIM_ / 64, (B_ * NQ) / 128), 256>>>(Ap, Wo, out, B_ * NQ, DIM_, HID_);
}